// round 3
// baseline (speedup 1.0000x reference)
#include <cuda_runtime.h>

#define Bb 8
#define Nn 16384
#define Kk 256
#define Dd 20

#define TP 32            // pixels per tile (4 per warp, 8 warps)
#define PPB 128          // pixels per block
#define NTILES (PPB/TP)  // 4
#define CH (Nn/PPB)      // 128 chunks per batch

#define EM (Bb*Kk*Dd)    // 40960
#define ES (Bb*Kk)       // 2048
#define G1 8             // stage-1 reduction groups
#define CPG (CH/G1)      // 16 chunks per group

// Per-(chunk,batch,k) partials. Plain stores -> deterministic reductions.
__device__ float g_partM[(long)CH * EM];   // ~21 MB, layout ch*EM + (bk*Dd+d)
__device__ float g_partS[CH * ES];         // ~1 MB,  layout ch*ES + bk
__device__ float g_p2M[G1 * EM];
__device__ float g_p2S[G1 * ES];

#define SMEM_FLOATS (Dd*Kk + Kk + TP*Dd + TP*Kk)   // 14208 floats = 56832 B

__global__ __launch_bounds__(256, 3)
void em_main(const float* __restrict__ gmean,
             const float* __restrict__ gfeat,
             const float* __restrict__ gvalid,
             const float* __restrict__ gadj)
{
    extern __shared__ float sm[];
    float* mean_sm = sm;               // [Dd][Kk]  transposed, 20 KB
    float* msq     = sm + Dd * Kk;     // [Kk]
    float* f_sm    = msq + Kk;         // [TP][Dd]
    float* p_sm    = f_sm + TP * Dd;   // [TP][Kk]  32 KB

    const int tid = threadIdx.x;
    const int kg  = tid & 31;          // lane
    const int w   = tid >> 5;          // warp 0..7; owns pixels 4w..4w+3
    const int b   = blockIdx.y;
    const int ch  = blockIdx.x;
    const int n0  = ch * PPB;

    // ---- stage mean[b] transposed [d][k] ----
    const float* mb = gmean + (long)b * Kk * Dd;
    for (int i = tid; i < Kk * Dd; i += 256) {
        int k = i / Dd, d = i - k * Dd;
        mean_sm[d * Kk + k] = mb[i];
    }
    __syncthreads();
    {
        float s = 0.f;
#pragma unroll
        for (int d = 0; d < Dd; d++) { float m = mean_sm[d * Kk + tid]; s += m * m; }
        msq[tid] = s;
    }
    __syncthreads();

    // tile-invariant: this lane's 8 cluster norms
    float mqa[8];
    {
        float4 q0 = *(const float4*)&msq[4 * kg];
        float4 q1 = *(const float4*)&msq[128 + 4 * kg];
        mqa[0] = q0.x; mqa[1] = q0.y; mqa[2] = q0.z; mqa[3] = q0.w;
        mqa[4] = q1.x; mqa[5] = q1.y; mqa[6] = q1.z; mqa[7] = q1.w;
    }

    // Phase-B accumulators: thread owns k = tid, live across all tiles
    float macc[Dd];
#pragma unroll
    for (int d = 0; d < Dd; d++) macc[d] = 0.f;
    float sacc = 0.f;

    for (int t = 0; t < NTILES; t++) {
        const int nbase = n0 + t * TP;
        if (t > 0) __syncthreads();   // previous Phase B done with f_sm/p_sm

        // ---- cooperative feature-tile load: 640 floats = 160 float4 ----
        if (tid < TP * Dd / 4) {
            ((float4*)f_sm)[tid] =
                ((const float4*)(gfeat + ((long)b * Nn + nbase) * Dd))[tid];
        }
        __syncthreads();

        // ===== Phase A: distances + softmax (2 passes of 2 pixels) =====
        const int p0 = 4 * w;
#pragma unroll
        for (int pass = 0; pass < 2; pass++) {
            const int pa = p0 + 2 * pass;
            const float* vr = gvalid + ((long)b * Nn + nbase + pa) * Kk;
            const float* ar = gadj   + ((long)b * Nn + nbase + pa) * Kk;

            // issue mask/offset loads up front; hidden under the dot loop
            float4 v00 = *(const float4*)(vr + 4 * kg);
            float4 v01 = *(const float4*)(vr + 128 + 4 * kg);
            float4 v10 = *(const float4*)(vr + 256 + 4 * kg);
            float4 v11 = *(const float4*)(vr + 384 + 4 * kg);
            float4 a00 = *(const float4*)(ar + 4 * kg);
            float4 a01 = *(const float4*)(ar + 128 + 4 * kg);
            float4 a10 = *(const float4*)(ar + 256 + 4 * kg);
            float4 a11 = *(const float4*)(ar + 384 + 4 * kg);

            float dot0[8], dot1[8];
#pragma unroll
            for (int j = 0; j < 8; j++) { dot0[j] = 0.f; dot1[j] = 0.f; }
            float fsq0 = 0.f, fsq1 = 0.f;

#pragma unroll
            for (int dq = 0; dq < 5; dq++) {
                float4 fva = *(const float4*)&f_sm[pa * Dd + 4 * dq];
                float4 fvb = *(const float4*)&f_sm[(pa + 1) * Dd + 4 * dq];
                float fra[4] = {fva.x, fva.y, fva.z, fva.w};
                float frb[4] = {fvb.x, fvb.y, fvb.z, fvb.w};
#pragma unroll
                for (int dd = 0; dd < 4; dd++) {
                    const int d = 4 * dq + dd;
                    float4 m0 = *(const float4*)&mean_sm[d * Kk + 4 * kg];
                    float4 m1 = *(const float4*)&mean_sm[d * Kk + 128 + 4 * kg];
                    float ma[8] = {m0.x, m0.y, m0.z, m0.w, m1.x, m1.y, m1.z, m1.w};
                    float fa = fra[dd], fb = frb[dd];
                    fsq0 += fa * fa;  fsq1 += fb * fb;
#pragma unroll
                    for (int j = 0; j < 8; j++) {
                        dot0[j] += fa * ma[j];
                        dot1[j] += fb * ma[j];
                    }
                }
            }

#pragma unroll
            for (int px = 0; px < 2; px++) {
                float va[8], aa[8];
                if (px == 0) {
                    va[0]=v00.x; va[1]=v00.y; va[2]=v00.z; va[3]=v00.w;
                    va[4]=v01.x; va[5]=v01.y; va[6]=v01.z; va[7]=v01.w;
                    aa[0]=a00.x; aa[1]=a00.y; aa[2]=a00.z; aa[3]=a00.w;
                    aa[4]=a01.x; aa[5]=a01.y; aa[6]=a01.z; aa[7]=a01.w;
                } else {
                    va[0]=v10.x; va[1]=v10.y; va[2]=v10.z; va[3]=v10.w;
                    va[4]=v11.x; va[5]=v11.y; va[6]=v11.z; va[7]=v11.w;
                    aa[0]=a10.x; aa[1]=a10.y; aa[2]=a10.z; aa[3]=a10.w;
                    aa[4]=a11.x; aa[5]=a11.y; aa[6]=a11.z; aa[7]=a11.w;
                }
                const float c = (px == 0) ? fsq0 : fsq1;
                const float* dot = (px == 0) ? dot0 : dot1;

                // g = dist^2*valid + adjust ; posterior = softmax(-g)  (2*STD^2==1)
                float g[8];
                float gmn = 3.4e38f;
#pragma unroll
                for (int j = 0; j < 8; j++) {
                    float dist = fmaf(-2.f, dot[j], c + mqa[j]);
                    g[j] = fmaf(dist, va[j], aa[j]);
                    gmn  = fminf(gmn, g[j]);
                }
#pragma unroll
                for (int o = 16; o > 0; o >>= 1)
                    gmn = fminf(gmn, __shfl_xor_sync(0xffffffffu, gmn, o));

                float e[8];
                float s = 0.f;
#pragma unroll
                for (int j = 0; j < 8; j++) { e[j] = __expf(gmn - g[j]); s += e[j]; }
#pragma unroll
                for (int o = 16; o > 0; o >>= 1)
                    s += __shfl_xor_sync(0xffffffffu, s, o);
                const float r = __fdividef(1.f, s);

                *(float4*)&p_sm[(pa + px) * Kk + 4 * kg] =
                    make_float4(e[0] * r, e[1] * r, e[2] * r, e[3] * r);
                *(float4*)&p_sm[(pa + px) * Kk + 128 + 4 * kg] =
                    make_float4(e[4] * r, e[5] * r, e[6] * r, e[7] * r);
            }
        }
        __syncthreads();

        // ============ Phase B: accumulate M[k][:] and S[k] ============
#pragma unroll 4
        for (int p = 0; p < TP; p++) {
            float pv = p_sm[p * Kk + tid];
            sacc += pv;
            const float4* f4 = (const float4*)&f_sm[p * Dd];
#pragma unroll
            for (int q = 0; q < Dd / 4; q++) {
                float4 fv = f4[q];
                macc[4 * q + 0] += pv * fv.x;
                macc[4 * q + 1] += pv * fv.y;
                macc[4 * q + 2] += pv * fv.z;
                macc[4 * q + 3] += pv * fv.w;
            }
        }
    }

    // ---- coalesced per-(chunk,b,k) partials ----
    const int bk = (b << 8) | tid;            // b*Kk + k
    g_partS[ch * ES + bk] = sacc;
    float* pm = &g_partM[(long)ch * EM + (long)bk * Dd];
#pragma unroll
    for (int d = 0; d < Dd; d++) pm[d] = macc[d];
}

// Stage 1: fold 128 chunks -> 8 groups, fully coalesced (thread = element).
__global__ void reduce1()
{
    const int i = blockIdx.x * 256 + threadIdx.x;
    if (i < G1 * EM) {
        const int g = i / EM, e = i - g * EM;
        float s = 0.f;
#pragma unroll 4
        for (int c = 0; c < CPG; c++)
            s += g_partM[(long)(g * CPG + c) * EM + e];
        g_p2M[i] = s;
    } else {
        const int j = i - G1 * EM;
        if (j < G1 * ES) {
            const int g = j / ES, e = j - g * ES;
            float s = 0.f;
#pragma unroll 4
            for (int c = 0; c < CPG; c++)
                s += g_partS[(g * CPG + c) * ES + e];
            g_p2S[j] = s;
        }
    }
}

// Stage 2: final 8-way sum + normalize.
__global__ void reduce2(float* __restrict__ out)
{
    const int e = blockIdx.x * 256 + threadIdx.x;   // over EM = 40960
    if (e >= EM) return;
    const int bk = e / Dd;
    float m = 0.f, s = 0.f;
#pragma unroll
    for (int g = 0; g < G1; g++) {
        m += g_p2M[g * EM + e];
        s += g_p2S[g * ES + bk];
    }
    out[e] = m / fmaxf(s, 1e-12f);
}

extern "C" void kernel_launch(void* const* d_in, const int* in_sizes, int n_in,
                              void* d_out, int out_size)
{
    const float* gmean  = (const float*)d_in[0];
    const float* gfeat  = (const float*)d_in[1];
    const float* gvalid = (const float*)d_in[2];
    const float* gadj   = (const float*)d_in[3];
    float* out = (float*)d_out;

    cudaFuncSetAttribute(em_main, cudaFuncAttributeMaxDynamicSharedMemorySize,
                         SMEM_FLOATS * (int)sizeof(float));

    dim3 grid(CH, Bb);
    em_main<<<grid, 256, SMEM_FLOATS * sizeof(float)>>>(gmean, gfeat, gvalid, gadj);
    reduce1<<<(G1 * EM + G1 * ES + 255) / 256, 256>>>();
    reduce2<<<(EM + 255) / 256, 256>>>(out);
}

// round 4
// speedup vs baseline: 2.3823x; 2.3823x over previous
#include <cuda_runtime.h>

#define Bb 8
#define Nn 16384
#define Kk 256
#define Dd 20

#define TP 32            // pixels per tile (4 per warp, 8 warps)
#define PPB 128          // pixels per block
#define NTILES (PPB/TP)  // 4
#define CH (Nn/PPB)      // 128 chunks per batch

#define EM (Bb*Kk*Dd)    // 40960
#define ES (Bb*Kk)       // 2048
#define G1 8             // stage-1 reduction groups
#define CPG (CH/G1)      // 16 chunks per group

// Per-(chunk,batch,k) partials. Plain stores -> deterministic reductions.
__device__ float g_partM[(long)CH * EM];   // ~21 MB, layout ch*EM + (bk*Dd+d)
__device__ float g_partS[CH * ES];         // ~1 MB,  layout ch*ES + bk
__device__ float g_p2M[G1 * EM];
__device__ float g_p2S[G1 * ES];

#define SMEM_FLOATS (Dd*Kk + Kk + TP*Dd + TP*Kk)   // 14208 floats = 56832 B

// ---- Blackwell packed f32x2 helpers (ptxas never emits these from C++) ----
typedef unsigned long long u64;

__device__ __forceinline__ u64 pack2(float v) {          // broadcast {v,v}
    u64 r; asm("mov.b64 %0, {%1,%1};" : "=l"(r) : "f"(v)); return r;
}
__device__ __forceinline__ u64 ffma2(u64 a, u64 b, u64 c) {
    u64 d; asm("fma.rn.f32x2 %0, %1, %2, %3;" : "=l"(d) : "l"(a), "l"(b), "l"(c));
    return d;
}
__device__ __forceinline__ void unpk(u64 v, float& lo, float& hi) {
    asm("mov.b64 {%0,%1}, %2;" : "=f"(lo), "=f"(hi) : "l"(v));
}

__global__ __launch_bounds__(256, 2)
void em_main(const float* __restrict__ gmean,
             const float* __restrict__ gfeat,
             const float* __restrict__ gvalid,
             const float* __restrict__ gadj)
{
    extern __shared__ float sm[];
    float* mean_sm = sm;               // [Dd][Kk]  transposed, 20 KB
    float* msq     = sm + Dd * Kk;     // [Kk]
    float* f_sm    = msq + Kk;         // [TP][Dd]
    float* p_sm    = f_sm + TP * Dd;   // [TP][Kk]  32 KB

    const int tid = threadIdx.x;
    const int kg  = tid & 31;          // lane
    const int w   = tid >> 5;          // warp 0..7; owns pixels 4w..4w+3
    const int b   = blockIdx.y;
    const int ch  = blockIdx.x;
    const int n0  = ch * PPB;

    // ---- stage mean[b] transposed [d][k] ----
    const float* mb = gmean + (long)b * Kk * Dd;
    for (int i = tid; i < Kk * Dd; i += 256) {
        int k = i / Dd, d = i - k * Dd;
        mean_sm[d * Kk + k] = mb[i];
    }
    __syncthreads();
    {
        float s = 0.f;
#pragma unroll
        for (int d = 0; d < Dd; d++) { float m = mean_sm[d * Kk + tid]; s += m * m; }
        msq[tid] = s;
    }
    __syncthreads();

    // tile-invariant: this lane's 8 cluster norms
    float mqa[8];
    {
        float4 q0 = *(const float4*)&msq[4 * kg];
        float4 q1 = *(const float4*)&msq[128 + 4 * kg];
        mqa[0] = q0.x; mqa[1] = q0.y; mqa[2] = q0.z; mqa[3] = q0.w;
        mqa[4] = q1.x; mqa[5] = q1.y; mqa[6] = q1.z; mqa[7] = q1.w;
    }

    // Phase-B accumulators: thread owns k = tid, packed pairs over d
    u64 macc2[Dd / 2];
#pragma unroll
    for (int q = 0; q < Dd / 2; q++) macc2[q] = 0ULL;
    float sacc = 0.f;

    for (int t = 0; t < NTILES; t++) {
        const int nbase = n0 + t * TP;
        if (t > 0) __syncthreads();   // previous Phase B done with f_sm/p_sm

        // ---- cooperative feature-tile load: 640 floats = 160 float4 ----
        if (tid < TP * Dd / 4) {
            ((float4*)f_sm)[tid] =
                ((const float4*)(gfeat + ((long)b * Nn + nbase) * Dd))[tid];
        }
        __syncthreads();

        // ================= Phase A: distances + softmax =================
        const int  p0   = 4 * w;
        const long rowb = ((long)b * Nn + nbase + p0) * Kk;
        const float* vr = gvalid + rowb;
        const float* ar = gadj   + rowb;

        // prefetch valid/adjust for px0 (hidden under dot loop)
        float4 cv0 = *(const float4*)(vr + 4 * kg);
        float4 cv1 = *(const float4*)(vr + 128 + 4 * kg);
        float4 ca0 = *(const float4*)(ar + 4 * kg);
        float4 ca1 = *(const float4*)(ar + 128 + 4 * kg);

        // packed dot accumulators: 4 pixels x 4 k-pairs
        u64 dot2[4][4];
#pragma unroll
        for (int p = 0; p < 4; p++)
#pragma unroll
            for (int j = 0; j < 4; j++) dot2[p][j] = 0ULL;
        float fsq[4] = {0.f, 0.f, 0.f, 0.f};

#pragma unroll
        for (int dq = 0; dq < 5; dq++) {
            float fr[4][4];
#pragma unroll
            for (int p = 0; p < 4; p++) {
                float4 fv = *(const float4*)&f_sm[(p0 + p) * Dd + 4 * dq];
                fr[p][0] = fv.x; fr[p][1] = fv.y; fr[p][2] = fv.z; fr[p][3] = fv.w;
            }
#pragma unroll
            for (int dd = 0; dd < 4; dd++) {
                const int d = 4 * dq + dd;
                ulonglong2 m0 = *(const ulonglong2*)&mean_sm[d * Kk + 4 * kg];
                ulonglong2 m1 = *(const ulonglong2*)&mean_sm[d * Kk + 128 + 4 * kg];
#pragma unroll
                for (int p = 0; p < 4; p++) {
                    const float f = fr[p][dd];
                    fsq[p] += f * f;
                    const u64 ff = pack2(f);
                    dot2[p][0] = ffma2(m0.x, ff, dot2[p][0]);
                    dot2[p][1] = ffma2(m0.y, ff, dot2[p][1]);
                    dot2[p][2] = ffma2(m1.x, ff, dot2[p][2]);
                    dot2[p][3] = ffma2(m1.y, ff, dot2[p][3]);
                }
            }
        }

#pragma unroll
        for (int p = 0; p < 4; p++) {
            // software pipeline: issue next pixel's valid/adjust loads now
            float4 nv0, nv1, na0, na1;
            if (p < 3) {
                const float* vrn = vr + (long)(p + 1) * Kk;
                const float* arn = ar + (long)(p + 1) * Kk;
                nv0 = *(const float4*)(vrn + 4 * kg);
                nv1 = *(const float4*)(vrn + 128 + 4 * kg);
                na0 = *(const float4*)(arn + 4 * kg);
                na1 = *(const float4*)(arn + 128 + 4 * kg);
            }
            float va[8] = {cv0.x, cv0.y, cv0.z, cv0.w, cv1.x, cv1.y, cv1.z, cv1.w};
            float aa[8] = {ca0.x, ca0.y, ca0.z, ca0.w, ca1.x, ca1.y, ca1.z, ca1.w};
            const float c = fsq[p];

            float dotv[8];
            unpk(dot2[p][0], dotv[0], dotv[1]);
            unpk(dot2[p][1], dotv[2], dotv[3]);
            unpk(dot2[p][2], dotv[4], dotv[5]);
            unpk(dot2[p][3], dotv[6], dotv[7]);

            // g = dist^2*valid + adjust ; posterior = exp(-g)/sum  (2*STD^2==1)
            // No max-subtraction: g >= 0 region here, exp(-g) in [~1e-53, 1],
            // sum over 256 terms dominated by nearest clusters -> fp32 safe.
            float e[8];
            float s = 0.f;
#pragma unroll
            for (int j = 0; j < 8; j++) {
                float dist = fmaf(-2.f, dotv[j], c + mqa[j]);
                float g    = fmaf(dist, va[j], aa[j]);
                e[j] = __expf(-g);
                s += e[j];
            }
#pragma unroll
            for (int o = 16; o > 0; o >>= 1)
                s += __shfl_xor_sync(0xffffffffu, s, o);
            const float r = __fdividef(1.f, s);

            *(float4*)&p_sm[(p0 + p) * Kk + 4 * kg] =
                make_float4(e[0] * r, e[1] * r, e[2] * r, e[3] * r);
            *(float4*)&p_sm[(p0 + p) * Kk + 128 + 4 * kg] =
                make_float4(e[4] * r, e[5] * r, e[6] * r, e[7] * r);

            if (p < 3) { cv0 = nv0; cv1 = nv1; ca0 = na0; ca1 = na1; }
        }
        __syncthreads();

        // ============ Phase B: accumulate M[k][:] and S[k] (packed) ============
#pragma unroll 4
        for (int p = 0; p < TP; p++) {
            const float pv = p_sm[p * Kk + tid];
            sacc += pv;
            const u64 pp = pack2(pv);
            const ulonglong2* f2 = (const ulonglong2*)&f_sm[p * Dd];  // 80B row, 16B aligned
#pragma unroll
            for (int q = 0; q < 5; q++) {
                ulonglong2 u = f2[q];
                macc2[2 * q]     = ffma2(u.x, pp, macc2[2 * q]);
                macc2[2 * q + 1] = ffma2(u.y, pp, macc2[2 * q + 1]);
            }
        }
    }

    // ---- coalesced per-(chunk,b,k) partials ----
    const int bk = (b << 8) | tid;            // b*Kk + k
    g_partS[ch * ES + bk] = sacc;
    float* pm = &g_partM[(long)ch * EM + (long)bk * Dd];
#pragma unroll
    for (int q = 0; q < Dd / 2; q++) {
        float lo, hi;
        unpk(macc2[q], lo, hi);
        pm[2 * q] = lo;  pm[2 * q + 1] = hi;
    }
}

// Stage 1: fold 128 chunks -> 8 groups, fully coalesced (thread = element).
__global__ void reduce1()
{
    const int i = blockIdx.x * 256 + threadIdx.x;
    if (i < G1 * EM) {
        const int g = i / EM, e = i - g * EM;
        float s = 0.f;
#pragma unroll 4
        for (int c = 0; c < CPG; c++)
            s += g_partM[(long)(g * CPG + c) * EM + e];
        g_p2M[i] = s;
    } else {
        const int j = i - G1 * EM;
        if (j < G1 * ES) {
            const int g = j / ES, e = j - g * ES;
            float s = 0.f;
#pragma unroll 4
            for (int c = 0; c < CPG; c++)
                s += g_partS[(g * CPG + c) * ES + e];
            g_p2S[j] = s;
        }
    }
}

// Stage 2: final 8-way sum + normalize.
__global__ void reduce2(float* __restrict__ out)
{
    const int e = blockIdx.x * 256 + threadIdx.x;   // over EM = 40960
    if (e >= EM) return;
    const int bk = e / Dd;
    float m = 0.f, s = 0.f;
#pragma unroll
    for (int g = 0; g < G1; g++) {
        m += g_p2M[g * EM + e];
        s += g_p2S[g * ES + bk];
    }
    out[e] = m / fmaxf(s, 1e-12f);
}

extern "C" void kernel_launch(void* const* d_in, const int* in_sizes, int n_in,
                              void* d_out, int out_size)
{
    const float* gmean  = (const float*)d_in[0];
    const float* gfeat  = (const float*)d_in[1];
    const float* gvalid = (const float*)d_in[2];
    const float* gadj   = (const float*)d_in[3];
    float* out = (float*)d_out;

    cudaFuncSetAttribute(em_main, cudaFuncAttributeMaxDynamicSharedMemorySize,
                         SMEM_FLOATS * (int)sizeof(float));

    dim3 grid(CH, Bb);
    em_main<<<grid, 256, SMEM_FLOATS * sizeof(float)>>>(gmean, gfeat, gvalid, gadj);
    reduce1<<<(G1 * EM + G1 * ES + 255) / 256, 256>>>();
    reduce2<<<(EM + 255) / 256, 256>>>(out);
}

// round 5
// speedup vs baseline: 2.5029x; 1.0507x over previous
#include <cuda_runtime.h>

#define Bb 8
#define Nn 16384
#define Kk 256
#define Dd 20

#define TP 32            // pixels per tile (4 per warp, 8 warps)
#define PPB 128          // pixels per block
#define NTILES (PPB/TP)  // 4
#define CH (Nn/PPB)      // 128 chunks per batch

#define EM (Bb*Kk*Dd)    // 40960
#define ES (Bb*Kk)       // 2048
#define G1 8             // stage-1 reduction groups
#define CPG (CH/G1)      // 16 chunks per group

// Per-(chunk,batch,k) partials. Plain stores -> deterministic reductions.
__device__ float g_partM[(long)CH * EM];   // ~21 MB, layout ch*EM + (bk*Dd+d)
__device__ float g_partS[CH * ES];         // ~1 MB,  layout ch*ES + bk
__device__ float g_p2M[G1 * EM];
__device__ float g_p2S[G1 * ES];

// mean(5120) + msq(256) + f_sm(640) + f_dup(1280) + rinv(32) + p_sm(8192)
#define SMEM_FLOATS (Dd*Kk + Kk + TP*Dd + TP*2*Dd + TP + TP*Kk)   // 15520

// ---- Blackwell packed f32x2 helpers (ptxas never emits these from C++) ----
typedef unsigned long long u64;

__device__ __forceinline__ u64 pack2(float v) {          // broadcast {v,v}
    u64 r; asm("mov.b64 %0, {%1,%1};" : "=l"(r) : "f"(v)); return r;
}
__device__ __forceinline__ u64 ffma2(u64 a, u64 b, u64 c) {
    u64 d; asm("fma.rn.f32x2 %0, %1, %2, %3;" : "=l"(d) : "l"(a), "l"(b), "l"(c));
    return d;
}
__device__ __forceinline__ void unpk(u64 v, float& lo, float& hi) {
    asm("mov.b64 {%0,%1}, %2;" : "=f"(lo), "=f"(hi) : "l"(v));
}

__global__ __launch_bounds__(256, 2)
void em_main(const float* __restrict__ gmean,
             const float* __restrict__ gfeat,
             const float* __restrict__ gvalid,
             const float* __restrict__ gadj)
{
    extern __shared__ float sm[];
    float* mean_sm = sm;                    // [Dd][Kk]  transposed
    float* msq     = mean_sm + Dd * Kk;     // [Kk]
    float* f_sm    = msq + Kk;              // [TP][Dd]      natural (Phase B)
    float* f_dup   = f_sm + TP * Dd;        // [TP][2*Dd]    {f,f} pairs (Phase A)
    float* rinv_sm = f_dup + TP * 2 * Dd;   // [TP]
    float* p_sm    = rinv_sm + TP;          // [TP][Kk]      unnormalized e

    const int tid = threadIdx.x;
    const int kg  = tid & 31;          // lane
    const int w   = tid >> 5;          // warp 0..7; owns pixels 4w..4w+3
    const int b   = blockIdx.y;
    const int ch  = blockIdx.x;
    const int n0  = ch * PPB;

    // ---- stage mean[b] transposed [d][k] ----
    const float* mb = gmean + (long)b * Kk * Dd;
    for (int i = tid; i < Kk * Dd; i += 256) {
        int k = i / Dd, d = i - k * Dd;
        mean_sm[d * Kk + k] = mb[i];
    }
    __syncthreads();
    {
        float s = 0.f;
#pragma unroll
        for (int d = 0; d < Dd; d++) { float m = mean_sm[d * Kk + tid]; s += m * m; }
        msq[tid] = s;
    }
    __syncthreads();

    // tile-invariant: this lane's 8 cluster norms
    float mqa[8];
    {
        float4 q0 = *(const float4*)&msq[4 * kg];
        float4 q1 = *(const float4*)&msq[128 + 4 * kg];
        mqa[0] = q0.x; mqa[1] = q0.y; mqa[2] = q0.z; mqa[3] = q0.w;
        mqa[4] = q1.x; mqa[5] = q1.y; mqa[6] = q1.z; mqa[7] = q1.w;
    }

    // Phase-B accumulators: thread owns k = tid, packed pairs over d
    u64 macc2[Dd / 2];
#pragma unroll
    for (int q = 0; q < Dd / 2; q++) macc2[q] = 0ULL;
    float sacc = 0.f;

    for (int t = 0; t < NTILES; t++) {
        const int nbase = n0 + t * TP;
        if (t > 0) __syncthreads();   // previous Phase B done with f_sm/p_sm

        // ---- cooperative feature-tile load; also build duplicated copy ----
        if (tid < TP * Dd / 4) {
            float4 fv = ((const float4*)(gfeat + ((long)b * Nn + nbase) * Dd))[tid];
            ((float4*)f_sm)[tid] = fv;
            const float vals[4] = {fv.x, fv.y, fv.z, fv.w};
#pragma unroll
            for (int jj = 0; jj < 4; jj++) {
                int e  = 4 * tid + jj;
                int px = e / Dd, d = e - px * Dd;
                *(float2*)&f_dup[px * (2 * Dd) + 2 * d] = make_float2(vals[jj], vals[jj]);
            }
        }
        __syncthreads();

        // ================= Phase A: distances + exp =================
        const int  p0   = 4 * w;
        const long rowb = ((long)b * Nn + nbase + p0) * Kk;
        const float* vr = gvalid + rowb;
        const float* ar = gadj   + rowb;

        // prefetch valid/adjust for px0 (hidden under dot loop)
        float4 cv0 = *(const float4*)(vr + 4 * kg);
        float4 cv1 = *(const float4*)(vr + 128 + 4 * kg);
        float4 ca0 = *(const float4*)(ar + 4 * kg);
        float4 ca1 = *(const float4*)(ar + 128 + 4 * kg);

        // packed dot + packed |f|^2 accumulators
        u64 dot2[4][4];
        u64 fsq2[4];
#pragma unroll
        for (int p = 0; p < 4; p++) {
            fsq2[p] = 0ULL;
#pragma unroll
            for (int j = 0; j < 4; j++) dot2[p][j] = 0ULL;
        }

#pragma unroll
        for (int d = 0; d < Dd; d++) {
            ulonglong2 m0 = *(const ulonglong2*)&mean_sm[d * Kk + 4 * kg];
            ulonglong2 m1 = *(const ulonglong2*)&mean_sm[d * Kk + 128 + 4 * kg];
#pragma unroll
            for (int p = 0; p < 4; p++) {
                const u64 ff = *(const u64*)&f_dup[(p0 + p) * (2 * Dd) + 2 * d]; // {f,f}
                fsq2[p]    = ffma2(ff, ff, fsq2[p]);
                dot2[p][0] = ffma2(m0.x, ff, dot2[p][0]);
                dot2[p][1] = ffma2(m0.y, ff, dot2[p][1]);
                dot2[p][2] = ffma2(m1.x, ff, dot2[p][2]);
                dot2[p][3] = ffma2(m1.y, ff, dot2[p][3]);
            }
        }

        float s4[4];
#pragma unroll
        for (int p = 0; p < 4; p++) {
            // software pipeline: issue next pixel's valid/adjust loads now
            float4 nv0, nv1, na0, na1;
            if (p < 3) {
                const float* vrn = vr + (long)(p + 1) * Kk;
                const float* arn = ar + (long)(p + 1) * Kk;
                nv0 = *(const float4*)(vrn + 4 * kg);
                nv1 = *(const float4*)(vrn + 128 + 4 * kg);
                na0 = *(const float4*)(arn + 4 * kg);
                na1 = *(const float4*)(arn + 128 + 4 * kg);
            }
            float va[8] = {cv0.x, cv0.y, cv0.z, cv0.w, cv1.x, cv1.y, cv1.z, cv1.w};
            float aa[8] = {ca0.x, ca0.y, ca0.z, ca0.w, ca1.x, ca1.y, ca1.z, ca1.w};

            float dotv[8];
            unpk(dot2[p][0], dotv[0], dotv[1]);
            unpk(dot2[p][1], dotv[2], dotv[3]);
            unpk(dot2[p][2], dotv[4], dotv[5]);
            unpk(dot2[p][3], dotv[6], dotv[7]);
            float c, chi;  unpk(fsq2[p], c, chi);

            // e = exp(-(dist*valid + adjust)); g >= 0 here so e <= 1 (fp32 safe).
            float e[8];
            float s = 0.f;
#pragma unroll
            for (int j = 0; j < 8; j++) {
                float dist = fmaf(-2.f, dotv[j], c + mqa[j]);
                e[j] = __expf(fmaf(dist, -va[j], -aa[j]));
                s += e[j];
            }
            s4[p] = s;

            // store UNNORMALIZED e; normalization deferred to Phase B
            *(float4*)&p_sm[(p0 + p) * Kk + 4 * kg] =
                make_float4(e[0], e[1], e[2], e[3]);
            *(float4*)&p_sm[(p0 + p) * Kk + 128 + 4 * kg] =
                make_float4(e[4], e[5], e[6], e[7]);

            if (p < 3) { cv0 = nv0; cv1 = nv1; ca0 = na0; ca1 = na1; }
        }

        // 4 interleaved butterfly sums (independent per round -> overlapped)
#pragma unroll
        for (int o = 16; o > 0; o >>= 1) {
            s4[0] += __shfl_xor_sync(0xffffffffu, s4[0], o);
            s4[1] += __shfl_xor_sync(0xffffffffu, s4[1], o);
            s4[2] += __shfl_xor_sync(0xffffffffu, s4[2], o);
            s4[3] += __shfl_xor_sync(0xffffffffu, s4[3], o);
        }
        if (kg < 4) {
            float sv = (kg == 0) ? s4[0] : (kg == 1) ? s4[1] : (kg == 2) ? s4[2] : s4[3];
            rinv_sm[p0 + kg] = __fdividef(1.f, sv);
        }
        __syncthreads();

        // ============ Phase B: accumulate M[k][:] and S[k] (packed) ============
#pragma unroll
        for (int p4 = 0; p4 < TP / 4; p4++) {
            const float4 rv = *(const float4*)&rinv_sm[4 * p4];
            const float rvs[4] = {rv.x, rv.y, rv.z, rv.w};
#pragma unroll
            for (int pi = 0; pi < 4; pi++) {
                const int p = 4 * p4 + pi;
                const float pv = p_sm[p * Kk + tid] * rvs[pi];
                sacc += pv;
                const u64 pp = pack2(pv);
                const ulonglong2* f2 = (const ulonglong2*)&f_sm[p * Dd];
#pragma unroll
                for (int q = 0; q < 5; q++) {
                    ulonglong2 u = f2[q];
                    macc2[2 * q]     = ffma2(u.x, pp, macc2[2 * q]);
                    macc2[2 * q + 1] = ffma2(u.y, pp, macc2[2 * q + 1]);
                }
            }
        }
    }

    // ---- coalesced per-(chunk,b,k) partials ----
    const int bk = (b << 8) | tid;            // b*Kk + k
    g_partS[ch * ES + bk] = sacc;
    float* pm = &g_partM[(long)ch * EM + (long)bk * Dd];
#pragma unroll
    for (int q = 0; q < Dd / 2; q++) {
        float lo, hi;
        unpk(macc2[q], lo, hi);
        pm[2 * q] = lo;  pm[2 * q + 1] = hi;
    }
}

// Stage 1: fold 128 chunks -> 8 groups, fully coalesced (thread = element).
__global__ void reduce1()
{
    const int i = blockIdx.x * 256 + threadIdx.x;
    if (i < G1 * EM) {
        const int g = i / EM, e = i - g * EM;
        float s = 0.f;
#pragma unroll 4
        for (int c = 0; c < CPG; c++)
            s += g_partM[(long)(g * CPG + c) * EM + e];
        g_p2M[i] = s;
    } else {
        const int j = i - G1 * EM;
        if (j < G1 * ES) {
            const int g = j / ES, e = j - g * ES;
            float s = 0.f;
#pragma unroll 4
            for (int c = 0; c < CPG; c++)
                s += g_partS[(g * CPG + c) * ES + e];
            g_p2S[j] = s;
        }
    }
}

// Stage 2: final 8-way sum + normalize.
__global__ void reduce2(float* __restrict__ out)
{
    const int e = blockIdx.x * 256 + threadIdx.x;   // over EM = 40960
    if (e >= EM) return;
    const int bk = e / Dd;
    float m = 0.f, s = 0.f;
#pragma unroll
    for (int g = 0; g < G1; g++) {
        m += g_p2M[g * EM + e];
        s += g_p2S[g * ES + bk];
    }
    out[e] = m / fmaxf(s, 1e-12f);
}

extern "C" void kernel_launch(void* const* d_in, const int* in_sizes, int n_in,
                              void* d_out, int out_size)
{
    const float* gmean  = (const float*)d_in[0];
    const float* gfeat  = (const float*)d_in[1];
    const float* gvalid = (const float*)d_in[2];
    const float* gadj   = (const float*)d_in[3];
    float* out = (float*)d_out;

    cudaFuncSetAttribute(em_main, cudaFuncAttributeMaxDynamicSharedMemorySize,
                         SMEM_FLOATS * (int)sizeof(float));

    dim3 grid(CH, Bb);
    em_main<<<grid, 256, SMEM_FLOATS * sizeof(float)>>>(gmean, gfeat, gvalid, gadj);
    reduce1<<<(G1 * EM + G1 * ES + 255) / 256, 256>>>();
    reduce2<<<(EM + 255) / 256, 256>>>(out);
}